// round 9
// baseline (speedup 1.0000x reference)
#include <cuda_runtime.h>
#include <math.h>

// ---------------------------------------------------------------------------
// PolyNetFP4Sim: x (B,1) -> 64 -> 64 -> 32 -> 1 MLP, FP4-quantized weights.
// Scalar input => the net is a smooth 1-D function f(x).
// SINGLE fused kernel:
//   blocks 0..63   : build 1024-pt table of f over [-6,6] (overlapped float4
//                    stencil st4[i] = t[i-1..i+2]), release global flag.
//   blocks 64..511 : prefetch x into regs (overlaps build), spin on flag,
//                    copy table to smem, cubic Lagrange interp, 12 elem/thr.
// Builders have lowest blockIdx -> always wave-1 resident -> spin is safe.
// Flag/done counters reset by last exiting block (graph-replay safe).
// ---------------------------------------------------------------------------

#define TABLE_N 1024
#define XMIN    (-6.0f)
#define H_STEP  (0.01171875f)              // 12/1024 exact in fp32
#define INV_H   (85.333333333333333f)      // 1024/12

#define NUM_BLOCKS   512
#define BUILD_BLOCKS 64
#define CONS_BLOCKS  (NUM_BLOCKS - BUILD_BLOCKS)   // 448
#define THREADS      256
#define GROUP_STRIDE (CONS_BLOCKS * THREADS)       // 114688 float4-groups
#define PREFETCH_K   3                             // 448*256*3*4 = 1376256 >= n

__device__ __align__(16) float g_t4[4 * TABLE_N];
__device__ int g_flag;   // builder arrivals (zero-init; reset each run)
__device__ int g_done;   // block exits      (zero-init; reset each run)

// Branch-free FP4 quantization (normals); denormal/zero cold path exact.
__device__ __forceinline__ float quant4(float w) {
    unsigned a  = __float_as_uint(w);
    unsigned ab = a & 0x7fffffffu;
    if (ab < 0x00800000u) {                 // zero or denormal (cold)
        if (ab == 0u) return 0.0f;
        int e; float m = frexpf(fabsf(w), &e);
        int qe = e + 1; qe = qe < 0 ? 0 : (qe > 3 ? 3 : qe);
        return copysignf(ldexpf((m >= 0.75f ? 1.5f : 1.0f) * 0.5f, qe - 1), w);
    }
    int ef = (int)(ab >> 23) - 127;
    int qe = ef + 2;
    qe = qe < 0 ? 0 : (qe > 3 ? 3 : qe);
    float base = __uint_as_float((unsigned)(125 + qe) << 23);   // 2^(qe-2)
    float val  = (ab & 0x00400000u) ? 1.5f * base : base;       // m >= 0.75
    return copysignf(val, w);
}

__device__ __forceinline__ float silu(float x) {
    return x / (1.0f + expf(-x));
}

// Cold path: exact evaluation for |x| outside the table range.
__device__ __noinline__ float eval_full(
    float x,
    const float* w1, const float* b1,
    const float* w2, const float* b2,
    const float* w3, const float* b3,
    const float* w4, const float* b4)
{
    float h1[64], h2[64];
    for (int j = 0; j < 64; j++)
        h1[j] = silu(fmaf(x, quant4(w1[j]), b1[j]));
    for (int j = 0; j < 64; j++) {
        float a = b2[j];
        for (int k = 0; k < 64; k++)
            a = fmaf(h1[k], quant4(w2[j * 64 + k]), a);
        h2[j] = silu(a);
    }
    float acc = b4[0];
    for (int j = 0; j < 32; j++) {
        float a = b3[j];
        for (int k = 0; k < 64; k++)
            a = fmaf(h2[k], quant4(w3[j * 64 + k]), a);
        acc = fmaf(silu(a), quant4(w4[j]), acc);
    }
    return acc;
}

// Shared memory: union of builder scratch and consumer table.
struct BuildSmem {
    float sw1[64], sb1[64], sb2[64], sb3[32], sw4[32];
    float sw2T[64 * 65];     // [k][j], padded
    float sw3T[64 * 33];     // [k][j], padded
    float sh1[8][2][64];
    float sh2[8][2][64];
};
union SmemU {
    BuildSmem b;
    float4 st4[TABLE_N];
};

__device__ __forceinline__ float interp_one(
    const float4* __restrict__ st4, float xv,
    const float* w1, const float* b1, const float* w2, const float* b2,
    const float* w3, const float* b3, const float* w4, const float* b4)
{
    float u  = (xv - XMIN) * INV_H;
    int   i0 = (int)u;                      // trunc == floor for u>=0
    if ((unsigned)(i0 - 1) <= (unsigned)(TABLE_N - 4)) {
        float s = u - (float)i0;
        float4 q = st4[i0];                 // (t[i0-1], t[i0], t[i0+1], t[i0+2])
        float sm1 = s - 1.0f, sm2 = s - 2.0f, sp1 = s + 1.0f;
        float c0 = -0.16666666666666666f * s   * sm1 * sm2;
        float c1 =  0.5f                 * sp1 * sm1 * sm2;
        float c2 = -0.5f                 * sp1 * s   * sm2;
        float c3 =  0.16666666666666666f * sp1 * s   * sm1;
        return c0 * q.x + c1 * q.y + c2 * q.z + c3 * q.w;
    }
    return eval_full(xv, w1, b1, w2, b2, w3, b3, w4, b4);
}

// ---------------------------------------------------------------------------
// Fused kernel.
// ---------------------------------------------------------------------------
__global__ void __launch_bounds__(256, 4)
fused_kernel(
    const float* __restrict__ x, float* __restrict__ out, int n,
    const float* __restrict__ w1, const float* __restrict__ b1,
    const float* __restrict__ w2, const float* __restrict__ b2,
    const float* __restrict__ w3, const float* __restrict__ b3,
    const float* __restrict__ w4, const float* __restrict__ b4)
{
    __shared__ SmemU smem;
    const int tid = threadIdx.x;
    const int bid = blockIdx.x;

    if (bid < BUILD_BLOCKS) {
        // ================= BUILDER =================
        BuildSmem& S = smem.b;
        for (int i = tid; i < 64; i += THREADS) {
            S.sw1[i] = quant4(w1[i]);
            S.sb1[i] = b1[i];
            S.sb2[i] = b2[i];
        }
        for (int i = tid; i < 32; i += THREADS) {
            S.sb3[i] = b3[i];
            S.sw4[i] = quant4(w4[i]);
        }
        for (int i = tid; i < 64 * 64; i += THREADS) {
            int j = i >> 6, k = i & 63;
            S.sw2T[k * 65 + j] = quant4(w2[i]);
        }
        for (int i = tid; i < 32 * 64; i += THREADS) {
            int j = i >> 6, k = i & 63;
            S.sw3T[k * 33 + j] = quant4(w3[i]);
        }
        __syncthreads();

        const int warp = tid >> 5;
        const int lane = tid & 31;
        const float b4v = b4[0];

        const int e0 = bid * 16 + warp * 2;          // 2 entries per warp
        const float x0 = XMIN + (float)e0 * H_STEP;
        const float x1 = x0 + H_STEP;

        // layer 1 (both entries)
        {
            float wq0 = S.sw1[lane], wq1 = S.sw1[lane + 32];
            float bb0 = S.sb1[lane], bb1 = S.sb1[lane + 32];
            S.sh1[warp][0][lane]      = silu(fmaf(x0, wq0, bb0));
            S.sh1[warp][0][lane + 32] = silu(fmaf(x0, wq1, bb1));
            S.sh1[warp][1][lane]      = silu(fmaf(x1, wq0, bb0));
            S.sh1[warp][1][lane + 32] = silu(fmaf(x1, wq1, bb1));
        }
        __syncwarp();

        // layer 2
        {
            float a00 = S.sb2[lane],      a01 = S.sb2[lane];
            float a10 = S.sb2[lane + 32], a11 = S.sb2[lane + 32];
            #pragma unroll
            for (int k = 0; k < 64; k++) {
                float wlo = S.sw2T[k * 65 + lane];
                float whi = S.sw2T[k * 65 + lane + 32];
                float h0 = S.sh1[warp][0][k];
                float h1 = S.sh1[warp][1][k];
                a00 = fmaf(h0, wlo, a00);
                a01 = fmaf(h1, wlo, a01);
                a10 = fmaf(h0, whi, a10);
                a11 = fmaf(h1, whi, a11);
            }
            S.sh2[warp][0][lane]      = silu(a00);
            S.sh2[warp][1][lane]      = silu(a01);
            S.sh2[warp][0][lane + 32] = silu(a10);
            S.sh2[warp][1][lane + 32] = silu(a11);
        }
        __syncwarp();

        // layer 3
        float c0 = S.sb3[lane], c1 = S.sb3[lane];
        #pragma unroll
        for (int k = 0; k < 64; k++) {
            float w = S.sw3T[k * 33 + lane];
            c0 = fmaf(S.sh2[warp][0][k], w, c0);
            c1 = fmaf(S.sh2[warp][1][k], w, c1);
        }
        float h30 = silu(c0);
        float h31 = silu(c1);

        // layer 4: two warp reductions
        float wq4 = S.sw4[lane];
        float p0 = h30 * wq4;
        float p1 = h31 * wq4;
        #pragma unroll
        for (int off = 16; off; off >>= 1) {
            p0 += __shfl_xor_sync(0xffffffffu, p0, off);
            p1 += __shfl_xor_sync(0xffffffffu, p1, off);
        }

        if (lane == 0) {
            #pragma unroll
            for (int i = 0; i < 2; i++) {
                int e = e0 + i;
                float t = (i == 0 ? p0 : p1) + b4v;
                if (e + 1 <= TABLE_N - 1) g_t4[4 * (e + 1) + 0] = t;
                g_t4[4 * e + 1] = t;
                if (e >= 1)               g_t4[4 * (e - 1) + 2] = t;
                if (e >= 2)               g_t4[4 * (e - 2) + 3] = t;
            }
        }

        // release: make table visible, then signal
        __threadfence();
        __syncthreads();
        if (tid == 0) atomicAdd(&g_flag, 1);
    } else {
        // ================= CONSUMER =================
        const int cid  = bid - BUILD_BLOCKS;
        const int base = cid * THREADS + tid;

        // Prefetch x into registers BEFORE waiting (overlaps the build).
        int    gids[PREFETCH_K];
        float4 xv[PREFETCH_K];
        bool   full[PREFETCH_K];
        #pragma unroll
        for (int k = 0; k < PREFETCH_K; k++) {
            int g = base + k * GROUP_STRIDE;
            gids[k] = g;
            full[k] = (g * 4 + 3 < n);
            if (full[k]) xv[k] = *reinterpret_cast<const float4*>(x + g * 4);
        }

        // Wait for builders (tid 0 spins; rest park at the barrier).
        if (tid == 0) {
            while (atomicAdd(&g_flag, 0) < BUILD_BLOCKS) __nanosleep(64);
            __threadfence();
        }
        __syncthreads();

        // Copy table to shared (bypass L1 to avoid any staleness).
        {
            const float4* src = reinterpret_cast<const float4*>(g_t4);
            for (int i = tid; i < TABLE_N; i += THREADS)
                smem.st4[i] = __ldcg(src + i);
        }
        __syncthreads();

        #pragma unroll
        for (int k = 0; k < PREFETCH_K; k++) {
            if (full[k]) {
                float4 r;
                r.x = interp_one(smem.st4, xv[k].x, w1, b1, w2, b2, w3, b3, w4, b4);
                r.y = interp_one(smem.st4, xv[k].y, w1, b1, w2, b2, w3, b3, w4, b4);
                r.z = interp_one(smem.st4, xv[k].z, w1, b1, w2, b2, w3, b3, w4, b4);
                r.w = interp_one(smem.st4, xv[k].w, w1, b1, w2, b2, w3, b3, w4, b4);
                *reinterpret_cast<float4*>(out + gids[k] * 4) = r;
            } else if (gids[k] * 4 < n) {               // ragged tail (cold)
                for (int e = gids[k] * 4; e < n; e++)
                    out[e] = interp_one(smem.st4, x[e], w1, b1, w2, b2, w3, b3, w4, b4);
            }
        }
        // generality: groups beyond PREFETCH_K strides (never for n<=1376256)
        for (int g = base + PREFETCH_K * GROUP_STRIDE; g * 4 < n; g += GROUP_STRIDE) {
            int e0 = g * 4;
            int eend = min(e0 + 4, n);
            for (int e = e0; e < eend; e++)
                out[e] = interp_one(smem.st4, x[e], w1, b1, w2, b2, w3, b3, w4, b4);
        }
    }

    // ============ exit + replay-safe counter reset ============
    __syncthreads();
    if (tid == 0) {
        __threadfence();
        int d = atomicAdd(&g_done, 1);
        if (d == NUM_BLOCKS - 1) {      // last block resets for next replay
            g_flag = 0;
            g_done = 0;
            __threadfence();
        }
    }
}

// ---------------------------------------------------------------------------
// Launch
// ---------------------------------------------------------------------------
extern "C" void kernel_launch(void* const* d_in, const int* in_sizes, int n_in,
                              void* d_out, int out_size)
{
    const float* x  = (const float*)d_in[0];
    const float* w1 = (const float*)d_in[1];
    const float* b1 = (const float*)d_in[2];
    const float* w2 = (const float*)d_in[3];
    const float* b2 = (const float*)d_in[4];
    const float* w3 = (const float*)d_in[5];
    const float* b3 = (const float*)d_in[6];
    const float* w4 = (const float*)d_in[7];
    const float* b4 = (const float*)d_in[8];
    float* out = (float*)d_out;
    const int n = in_sizes[0];

    fused_kernel<<<NUM_BLOCKS, THREADS>>>(x, out, n,
                                          w1, b1, w2, b2, w3, b3, w4, b4);
}

// round 10
// speedup vs baseline: 1.1175x; 1.1175x over previous
#include <cuda_runtime.h>
#include <math.h>

// ---------------------------------------------------------------------------
// PolyNetFP4Sim: x (B,1) -> 64 -> 64 -> 32 -> 1 MLP, FP4-quantized weights.
// Scalar input => the net is a smooth 1-D function f(x).
//   K1: build 256-pt table of f over [-6,6]; write OVERLAPPED float4 stencil
//       st4[i] = (t[i-1], t[i], t[i+1], t[i+2])  (4KB total).
//   K2: apply: cubic Lagrange from the L1-RESIDENT global stencil (no smem,
//       no sync, no per-block copy); 8 elems/thread, grid 512.
// |x| outside table (never for this dataset) -> exact direct evaluation.
// ---------------------------------------------------------------------------

#define TABLE_N 256
#define XMIN    (-6.0f)
#define H_STEP  (0.046875f)                 // 12/256 exact in fp32
#define INV_H   (21.333333333333333f)       // 256/12

__device__ __align__(16) float g_t4[4 * TABLE_N];   // overlapped stencil

// Branch-free FP4 quantization (normals); denormal/zero cold path exact.
__device__ __forceinline__ float quant4(float w) {
    unsigned a  = __float_as_uint(w);
    unsigned ab = a & 0x7fffffffu;
    if (ab < 0x00800000u) {                 // zero or denormal (cold)
        if (ab == 0u) return 0.0f;
        int e; float m = frexpf(fabsf(w), &e);
        int qe = e + 1; qe = qe < 0 ? 0 : (qe > 3 ? 3 : qe);
        return copysignf(ldexpf((m >= 0.75f ? 1.5f : 1.0f) * 0.5f, qe - 1), w);
    }
    int ef = (int)(ab >> 23) - 127;
    int qe = ef + 2;
    qe = qe < 0 ? 0 : (qe > 3 ? 3 : qe);
    float base = __uint_as_float((unsigned)(125 + qe) << 23);   // 2^(qe-2)
    float val  = (ab & 0x00400000u) ? 1.5f * base : base;       // m >= 0.75
    return copysignf(val, w);
}

__device__ __forceinline__ float silu(float x) {
    return x / (1.0f + expf(-x));
}

// Cold path: exact evaluation for |x| outside the table range.
__device__ __noinline__ float eval_full(
    float x,
    const float* w1, const float* b1,
    const float* w2, const float* b2,
    const float* w3, const float* b3,
    const float* w4, const float* b4)
{
    float h1[64], h2[64];
    for (int j = 0; j < 64; j++)
        h1[j] = silu(fmaf(x, quant4(w1[j]), b1[j]));
    for (int j = 0; j < 64; j++) {
        float a = b2[j];
        for (int k = 0; k < 64; k++)
            a = fmaf(h1[k], quant4(w2[j * 64 + k]), a);
        h2[j] = silu(a);
    }
    float acc = b4[0];
    for (int j = 0; j < 32; j++) {
        float a = b3[j];
        for (int k = 0; k < 64; k++)
            a = fmaf(h2[k], quant4(w3[j * 64 + k]), a);
        acc = fmaf(silu(a), quant4(w4[j]), acc);
    }
    return acc;
}

// ---------------------------------------------------------------------------
// K1: build. 16 blocks x 8 warps x 2 batched entries = 256 entries.
// ---------------------------------------------------------------------------
#define WARPS_PER_BLOCK 8
#define ENT_PER_BLOCK (2 * WARPS_PER_BLOCK)

__global__ void __launch_bounds__(256)
build_table_kernel(
    const float* __restrict__ w1, const float* __restrict__ b1,
    const float* __restrict__ w2, const float* __restrict__ b2,
    const float* __restrict__ w3, const float* __restrict__ b3,
    const float* __restrict__ w4, const float* __restrict__ b4)
{
    __shared__ float sw1[64], sb1[64], sb2[64], sb3[32], sw4[32];
    __shared__ float sw2T[64 * 65];                 // [k][j], padded
    __shared__ float sw3T[64 * 33];                 // [k][j], padded
    __shared__ float sh1[WARPS_PER_BLOCK][2][64];
    __shared__ float sh2[WARPS_PER_BLOCK][2][64];

    const int tid = threadIdx.x;

    for (int i = tid; i < 64; i += 256) {
        sw1[i] = quant4(w1[i]);
        sb1[i] = b1[i];
        sb2[i] = b2[i];
    }
    for (int i = tid; i < 32; i += 256) {
        sb3[i] = b3[i];
        sw4[i] = quant4(w4[i]);
    }
    for (int i = tid; i < 64 * 64; i += 256) {
        int j = i >> 6, k = i & 63;
        sw2T[k * 65 + j] = quant4(w2[i]);
    }
    for (int i = tid; i < 32 * 64; i += 256) {
        int j = i >> 6, k = i & 63;
        sw3T[k * 33 + j] = quant4(w3[i]);
    }
    __syncthreads();

    const int warp = tid >> 5;
    const int lane = tid & 31;
    const float b4v = b4[0];

    const int e0 = blockIdx.x * ENT_PER_BLOCK + warp * 2;   // entries e0, e0+1
    const float x0 = XMIN + (float)e0 * H_STEP;
    const float x1 = x0 + H_STEP;

    // layer 1 (both entries)
    {
        float wq0 = sw1[lane], wq1 = sw1[lane + 32];
        float bb0 = sb1[lane], bb1 = sb1[lane + 32];
        sh1[warp][0][lane]      = silu(fmaf(x0, wq0, bb0));
        sh1[warp][0][lane + 32] = silu(fmaf(x0, wq1, bb1));
        sh1[warp][1][lane]      = silu(fmaf(x1, wq0, bb0));
        sh1[warp][1][lane + 32] = silu(fmaf(x1, wq1, bb1));
    }
    __syncwarp();

    // layer 2: lane j -> outputs j, j+32, both entries (weights reused)
    {
        float a00 = sb2[lane],      a01 = sb2[lane];
        float a10 = sb2[lane + 32], a11 = sb2[lane + 32];
        #pragma unroll
        for (int k = 0; k < 64; k++) {
            float wlo = sw2T[k * 65 + lane];
            float whi = sw2T[k * 65 + lane + 32];
            float h0 = sh1[warp][0][k];
            float h1 = sh1[warp][1][k];
            a00 = fmaf(h0, wlo, a00);
            a01 = fmaf(h1, wlo, a01);
            a10 = fmaf(h0, whi, a10);
            a11 = fmaf(h1, whi, a11);
        }
        sh2[warp][0][lane]      = silu(a00);
        sh2[warp][1][lane]      = silu(a01);
        sh2[warp][0][lane + 32] = silu(a10);
        sh2[warp][1][lane + 32] = silu(a11);
    }
    __syncwarp();

    // layer 3: lane j -> output j, both entries
    float c0 = sb3[lane], c1 = sb3[lane];
    #pragma unroll
    for (int k = 0; k < 64; k++) {
        float w = sw3T[k * 33 + lane];
        c0 = fmaf(sh2[warp][0][k], w, c0);
        c1 = fmaf(sh2[warp][1][k], w, c1);
    }
    float h30 = silu(c0);
    float h31 = silu(c1);

    // layer 4: two warp reductions, one shuffle ladder
    float wq4 = sw4[lane];
    float p0 = h30 * wq4;
    float p1 = h31 * wq4;
    #pragma unroll
    for (int off = 16; off; off >>= 1) {
        p0 += __shfl_xor_sync(0xffffffffu, p0, off);
        p1 += __shfl_xor_sync(0xffffffffu, p1, off);
    }

    if (lane == 0) {
        #pragma unroll
        for (int i = 0; i < 2; i++) {
            int e = e0 + i;
            float t = (i == 0 ? p0 : p1) + b4v;
            // scatter into overlapped stencil: st4[i] = t[i-1..i+2]
            if (e + 1 <= TABLE_N - 1) g_t4[4 * (e + 1) + 0] = t;
            g_t4[4 * e + 1] = t;
            if (e >= 1)               g_t4[4 * (e - 1) + 2] = t;
            if (e >= 2)               g_t4[4 * (e - 2) + 3] = t;
        }
    }
}

// ---------------------------------------------------------------------------
// K2: apply. No smem: stencil read straight from the 4KB L1-resident global
// table. One LDG.128 per element. 8 elems/thread, grid 512.
// ---------------------------------------------------------------------------
__device__ __forceinline__ float interp_one(
    float xv,
    const float* w1, const float* b1, const float* w2, const float* b2,
    const float* w3, const float* b3, const float* w4, const float* b4)
{
    float u  = (xv - XMIN) * INV_H;
    int   i0 = (int)u;                      // trunc == floor for u >= 0
    if ((unsigned)(i0 - 1) <= (unsigned)(TABLE_N - 4)) {
        float s = u - (float)i0;
        float4 q = __ldg(reinterpret_cast<const float4*>(g_t4) + i0);
        float sm1 = s - 1.0f, sm2 = s - 2.0f, sp1 = s + 1.0f;
        float c0 = -0.16666666666666666f * s   * sm1 * sm2;
        float c1 =  0.5f                 * sp1 * sm1 * sm2;
        float c2 = -0.5f                 * sp1 * s   * sm2;
        float c3 =  0.16666666666666666f * sp1 * s   * sm1;
        return c0 * q.x + c1 * q.y + c2 * q.z + c3 * q.w;
    }
    return eval_full(xv, w1, b1, w2, b2, w3, b3, w4, b4);
}

__global__ void __launch_bounds__(256)
apply_kernel(
    const float* __restrict__ x, float* __restrict__ out, int n,
    const float* __restrict__ w1, const float* __restrict__ b1,
    const float* __restrict__ w2, const float* __restrict__ b2,
    const float* __restrict__ w3, const float* __restrict__ b3,
    const float* __restrict__ w4, const float* __restrict__ b4)
{
    const int gid = blockIdx.x * blockDim.x + threadIdx.x;
    const int e0  = gid * 8;

    if (e0 + 7 < n) {
        // both 16B x-loads in flight before any use
        float4 xa = *reinterpret_cast<const float4*>(x + e0);
        float4 xb = *reinterpret_cast<const float4*>(x + e0 + 4);
        float4 ra, rb;
        ra.x = interp_one(xa.x, w1, b1, w2, b2, w3, b3, w4, b4);
        ra.y = interp_one(xa.y, w1, b1, w2, b2, w3, b3, w4, b4);
        ra.z = interp_one(xa.z, w1, b1, w2, b2, w3, b3, w4, b4);
        ra.w = interp_one(xa.w, w1, b1, w2, b2, w3, b3, w4, b4);
        rb.x = interp_one(xb.x, w1, b1, w2, b2, w3, b3, w4, b4);
        rb.y = interp_one(xb.y, w1, b1, w2, b2, w3, b3, w4, b4);
        rb.z = interp_one(xb.z, w1, b1, w2, b2, w3, b3, w4, b4);
        rb.w = interp_one(xb.w, w1, b1, w2, b2, w3, b3, w4, b4);
        *reinterpret_cast<float4*>(out + e0)     = ra;
        *reinterpret_cast<float4*>(out + e0 + 4) = rb;
    } else {
        for (int e = e0; e < n; e++)
            out[e] = interp_one(x[e], w1, b1, w2, b2, w3, b3, w4, b4);
    }
}

// ---------------------------------------------------------------------------
// Launch
// ---------------------------------------------------------------------------
extern "C" void kernel_launch(void* const* d_in, const int* in_sizes, int n_in,
                              void* d_out, int out_size)
{
    const float* x  = (const float*)d_in[0];
    const float* w1 = (const float*)d_in[1];
    const float* b1 = (const float*)d_in[2];
    const float* w2 = (const float*)d_in[3];
    const float* b2 = (const float*)d_in[4];
    const float* w3 = (const float*)d_in[5];
    const float* b3 = (const float*)d_in[6];
    const float* w4 = (const float*)d_in[7];
    const float* b4 = (const float*)d_in[8];
    float* out = (float*)d_out;
    const int n = in_sizes[0];

    build_table_kernel<<<TABLE_N / ENT_PER_BLOCK, 256>>>(w1, b1, w2, b2, w3, b3, w4, b4);

    const int nvec   = (n + 7) / 8;
    const int blocks = (nvec + 255) / 256;
    apply_kernel<<<blocks, 256>>>(x, out, n, w1, b1, w2, b2, w3, b3, w4, b4);
}

// round 11
// speedup vs baseline: 1.1196x; 1.0019x over previous
#include <cuda_runtime.h>
#include <math.h>

// ---------------------------------------------------------------------------
// PolyNetFP4Sim: x (B,1) -> 64 -> 64 -> 32 -> 1 MLP, FP4-quantized weights.
// Scalar input => the net is a smooth 1-D function f(x).
//   K1: build 256-pt table of f over [-6,6]; OVERLAPPED float4 stencil
//       st4[i] = (t[i-1], t[i], t[i+1], t[i+2]) (4KB). Fires PDL trigger.
//   K2: apply (PDL): prefetch x, cudaGridDependencySynchronize, then cubic
//       Lagrange from the L1-resident global stencil. Batched gathers,
//       magic-number rounding (no F2I/I2F), 8 elems/thread, grid 512.
// |x| outside table (never for this dataset) -> exact direct evaluation.
// ---------------------------------------------------------------------------

#define TABLE_N 256
#define XMIN    (-6.0f)
#define H_STEP  (0.046875f)                 // 12/256 exact in fp32
#define INV_H   (21.333333333333333f)       // 256/12
#define U_OFF   (128.0f)                    // -XMIN*INV_H, exact
#define MAGIC   (12582912.0f)               // 1.5 * 2^23

__device__ __align__(16) float g_t4[4 * TABLE_N];   // overlapped stencil

// Branch-free FP4 quantization (normals); denormal/zero cold path exact.
__device__ __forceinline__ float quant4(float w) {
    unsigned a  = __float_as_uint(w);
    unsigned ab = a & 0x7fffffffu;
    if (ab < 0x00800000u) {                 // zero or denormal (cold)
        if (ab == 0u) return 0.0f;
        int e; float m = frexpf(fabsf(w), &e);
        int qe = e + 1; qe = qe < 0 ? 0 : (qe > 3 ? 3 : qe);
        return copysignf(ldexpf((m >= 0.75f ? 1.5f : 1.0f) * 0.5f, qe - 1), w);
    }
    int ef = (int)(ab >> 23) - 127;
    int qe = ef + 2;
    qe = qe < 0 ? 0 : (qe > 3 ? 3 : qe);
    float base = __uint_as_float((unsigned)(125 + qe) << 23);   // 2^(qe-2)
    float val  = (ab & 0x00400000u) ? 1.5f * base : base;       // m >= 0.75
    return copysignf(val, w);
}

__device__ __forceinline__ float silu(float x) {
    return x / (1.0f + expf(-x));
}

// Cold path: exact evaluation for |x| outside the table range.
__device__ __noinline__ float eval_full(
    float x,
    const float* w1, const float* b1,
    const float* w2, const float* b2,
    const float* w3, const float* b3,
    const float* w4, const float* b4)
{
    float h1[64], h2[64];
    for (int j = 0; j < 64; j++)
        h1[j] = silu(fmaf(x, quant4(w1[j]), b1[j]));
    for (int j = 0; j < 64; j++) {
        float a = b2[j];
        for (int k = 0; k < 64; k++)
            a = fmaf(h1[k], quant4(w2[j * 64 + k]), a);
        h2[j] = silu(a);
    }
    float acc = b4[0];
    for (int j = 0; j < 32; j++) {
        float a = b3[j];
        for (int k = 0; k < 64; k++)
            a = fmaf(h2[k], quant4(w3[j * 64 + k]), a);
        acc = fmaf(silu(a), quant4(w4[j]), acc);
    }
    return acc;
}

// ---------------------------------------------------------------------------
// K1: build. 16 blocks x 8 warps x 2 batched entries = 256 entries.
// ---------------------------------------------------------------------------
#define WARPS_PER_BLOCK 8
#define ENT_PER_BLOCK (2 * WARPS_PER_BLOCK)

__global__ void __launch_bounds__(256)
build_table_kernel(
    const float* __restrict__ w1, const float* __restrict__ b1,
    const float* __restrict__ w2, const float* __restrict__ b2,
    const float* __restrict__ w3, const float* __restrict__ b3,
    const float* __restrict__ w4, const float* __restrict__ b4)
{
    __shared__ float sw1[64], sb1[64], sb2[64], sb3[32], sw4[32];
    __shared__ float sw2T[64 * 65];                 // [k][j], padded
    __shared__ float sw3T[64 * 33];                 // [k][j], padded
    __shared__ float sh1[WARPS_PER_BLOCK][2][64];
    __shared__ float sh2[WARPS_PER_BLOCK][2][64];

    const int tid = threadIdx.x;

    for (int i = tid; i < 64; i += 256) {
        sw1[i] = quant4(w1[i]);
        sb1[i] = b1[i];
        sb2[i] = b2[i];
    }
    for (int i = tid; i < 32; i += 256) {
        sb3[i] = b3[i];
        sw4[i] = quant4(w4[i]);
    }
    for (int i = tid; i < 64 * 64; i += 256) {
        int j = i >> 6, k = i & 63;
        sw2T[k * 65 + j] = quant4(w2[i]);
    }
    for (int i = tid; i < 32 * 64; i += 256) {
        int j = i >> 6, k = i & 63;
        sw3T[k * 33 + j] = quant4(w3[i]);
    }
    __syncthreads();

    const int warp = tid >> 5;
    const int lane = tid & 31;
    const float b4v = b4[0];

    const int e0 = blockIdx.x * ENT_PER_BLOCK + warp * 2;   // entries e0, e0+1
    const float x0 = XMIN + (float)e0 * H_STEP;
    const float x1 = x0 + H_STEP;

    // layer 1 (both entries)
    {
        float wq0 = sw1[lane], wq1 = sw1[lane + 32];
        float bb0 = sb1[lane], bb1 = sb1[lane + 32];
        sh1[warp][0][lane]      = silu(fmaf(x0, wq0, bb0));
        sh1[warp][0][lane + 32] = silu(fmaf(x0, wq1, bb1));
        sh1[warp][1][lane]      = silu(fmaf(x1, wq0, bb0));
        sh1[warp][1][lane + 32] = silu(fmaf(x1, wq1, bb1));
    }
    __syncwarp();

    // layer 2: lane j -> outputs j, j+32, both entries (weights reused)
    {
        float a00 = sb2[lane],      a01 = sb2[lane];
        float a10 = sb2[lane + 32], a11 = sb2[lane + 32];
        #pragma unroll
        for (int k = 0; k < 64; k++) {
            float wlo = sw2T[k * 65 + lane];
            float whi = sw2T[k * 65 + lane + 32];
            float h0 = sh1[warp][0][k];
            float h1 = sh1[warp][1][k];
            a00 = fmaf(h0, wlo, a00);
            a01 = fmaf(h1, wlo, a01);
            a10 = fmaf(h0, whi, a10);
            a11 = fmaf(h1, whi, a11);
        }
        sh2[warp][0][lane]      = silu(a00);
        sh2[warp][1][lane]      = silu(a01);
        sh2[warp][0][lane + 32] = silu(a10);
        sh2[warp][1][lane + 32] = silu(a11);
    }
    __syncwarp();

    // layer 3: lane j -> output j, both entries
    float c0 = sb3[lane], c1 = sb3[lane];
    #pragma unroll
    for (int k = 0; k < 64; k++) {
        float w = sw3T[k * 33 + lane];
        c0 = fmaf(sh2[warp][0][k], w, c0);
        c1 = fmaf(sh2[warp][1][k], w, c1);
    }
    float h30 = silu(c0);
    float h31 = silu(c1);

    // layer 4: two warp reductions, one shuffle ladder
    float wq4 = sw4[lane];
    float p0 = h30 * wq4;
    float p1 = h31 * wq4;
    #pragma unroll
    for (int off = 16; off; off >>= 1) {
        p0 += __shfl_xor_sync(0xffffffffu, p0, off);
        p1 += __shfl_xor_sync(0xffffffffu, p1, off);
    }

    if (lane == 0) {
        #pragma unroll
        for (int i = 0; i < 2; i++) {
            int e = e0 + i;
            float t = (i == 0 ? p0 : p1) + b4v;
            if (e + 1 <= TABLE_N - 1) g_t4[4 * (e + 1) + 0] = t;
            g_t4[4 * e + 1] = t;
            if (e >= 1)               g_t4[4 * (e - 1) + 2] = t;
            if (e >= 2)               g_t4[4 * (e - 2) + 3] = t;
        }
    }

    // PDL release: table visible at device scope, then fire completion.
    __threadfence();
    __syncthreads();
#if __CUDA_ARCH__ >= 900
    cudaTriggerProgrammaticLaunchCompletion();
#endif
}

// ---------------------------------------------------------------------------
// K2: apply. Batched 4-wide interp: all indices, then all gathers, then all
// math. Magic-number round-to-nearest (node stencil valid for s in [-.5,.5]).
// ---------------------------------------------------------------------------
__device__ __forceinline__ void interp4(
    float4 xv, float4* r,
    const float* w1, const float* b1, const float* w2, const float* b2,
    const float* w3, const float* b3, const float* w4, const float* b4)
{
    const float4* t4 = reinterpret_cast<const float4*>(g_t4);
    float xs[4] = {xv.x, xv.y, xv.z, xv.w};
    float u[4], s[4];
    int   idx[4];
    bool  ok[4];

    #pragma unroll
    for (int k = 0; k < 4; k++) {
        u[k] = fmaf(xs[k], INV_H, U_OFF);
        float m = u[k] + MAGIC;                 // round-to-nearest int
        idx[k] = __float_as_int(m) & 0xFF;      // masked: always in-bounds
        s[k] = u[k] - (m - MAGIC);              // s in [-0.5, 0.5]
        ok[k] = (u[k] > 1.0f) && (u[k] < 253.0f);
    }

    float4 q[4];
    #pragma unroll
    for (int k = 0; k < 4; k++)
        q[k] = __ldg(t4 + idx[k]);              // 4 gathers in flight

    float rs[4];
    #pragma unroll
    for (int k = 0; k < 4; k++) {
        if (ok[k]) {
            float sv  = s[k];
            float sm1 = sv - 1.0f, sm2 = sv - 2.0f, sp1 = sv + 1.0f;
            float a  = sv * sm1;
            float bb = sp1 * sm2;
            float c0 = a  * sm2 * -0.16666666666666666f;
            float c3 = a  * sp1 *  0.16666666666666666f;
            float c1 = bb * sm1 *  0.5f;
            float c2 = bb * sv  * -0.5f;
            rs[k] = fmaf(c0, q[k].x, fmaf(c1, q[k].y,
                    fmaf(c2, q[k].z, c3 * q[k].w)));
        } else {
            rs[k] = eval_full(xs[k], w1, b1, w2, b2, w3, b3, w4, b4);
        }
    }
    *r = make_float4(rs[0], rs[1], rs[2], rs[3]);
}

__global__ void __launch_bounds__(256, 4)
apply_kernel(
    const float* __restrict__ x, float* __restrict__ out, int n,
    const float* __restrict__ w1, const float* __restrict__ b1,
    const float* __restrict__ w2, const float* __restrict__ b2,
    const float* __restrict__ w3, const float* __restrict__ b3,
    const float* __restrict__ w4, const float* __restrict__ b4)
{
    const int gid = blockIdx.x * blockDim.x + threadIdx.x;
    const int e0  = gid * 8;
    const bool fullv = (e0 + 7 < n);

    // Prefetch x BEFORE waiting on the builder grid (overlaps the build).
    float4 xa, xb;
    if (fullv) {
        xa = *reinterpret_cast<const float4*>(x + e0);
        xb = *reinterpret_cast<const float4*>(x + e0 + 4);
    }

#if __CUDA_ARCH__ >= 900
    cudaGridDependencySynchronize();            // table ready past this point
#endif

    if (fullv) {
        float4 ra, rb;
        interp4(xa, &ra, w1, b1, w2, b2, w3, b3, w4, b4);
        interp4(xb, &rb, w1, b1, w2, b2, w3, b3, w4, b4);
        *reinterpret_cast<float4*>(out + e0)     = ra;
        *reinterpret_cast<float4*>(out + e0 + 4) = rb;
    } else {
        for (int e = e0; e < n; e++) {
            float xv = x[e];
            float4 r4;
            interp4(make_float4(xv, xv, xv, xv), &r4,
                    w1, b1, w2, b2, w3, b3, w4, b4);
            out[e] = r4.x;
        }
    }
}

// ---------------------------------------------------------------------------
// Launch: build normally, apply with Programmatic Stream Serialization so it
// launches while build drains; apply syncs internally before consuming.
// ---------------------------------------------------------------------------
extern "C" void kernel_launch(void* const* d_in, const int* in_sizes, int n_in,
                              void* d_out, int out_size)
{
    const float* x  = (const float*)d_in[0];
    const float* w1 = (const float*)d_in[1];
    const float* b1 = (const float*)d_in[2];
    const float* w2 = (const float*)d_in[3];
    const float* b2 = (const float*)d_in[4];
    const float* w3 = (const float*)d_in[5];
    const float* b3 = (const float*)d_in[6];
    const float* w4 = (const float*)d_in[7];
    const float* b4 = (const float*)d_in[8];
    float* out = (float*)d_out;
    const int n = in_sizes[0];

    build_table_kernel<<<TABLE_N / ENT_PER_BLOCK, 256>>>(w1, b1, w2, b2, w3, b3, w4, b4);

    const int nvec   = (n + 7) / 8;
    const int blocks = (nvec + 255) / 256;

    cudaLaunchConfig_t cfg = {};
    cfg.gridDim  = dim3((unsigned)blocks);
    cfg.blockDim = dim3(256);
    cfg.dynamicSmemBytes = 0;
    cfg.stream = 0;
    cudaLaunchAttribute attrs[1];
    attrs[0].id = cudaLaunchAttributeProgrammaticStreamSerialization;
    attrs[0].val.programmaticStreamSerializationAllowed = 1;
    cfg.attrs = attrs;
    cfg.numAttrs = 1;

    cudaError_t err = cudaLaunchKernelEx(&cfg, apply_kernel, x, out, n,
                                         w1, b1, w2, b2, w3, b3, w4, b4);
    if (err != cudaSuccess) {
        // Fallback: plain sequential launch (still correct).
        apply_kernel<<<blocks, 256>>>(x, out, n, w1, b1, w2, b2, w3, b3, w4, b4);
    }
}